// round 17
// baseline (speedup 1.0000x reference)
#include <cuda_runtime.h>
#include <math.h>

#define N   8192
#define NZ  256
#define NC  128
#define DT_ 0.1f

// k_rz: z = W_rz @ r, 8-way column split, 4 rows per block -> 512 blocks
#define SPL_A 8
#define CHA4  (N / 4 / SPL_A)          // 256 float4 per column chunk

// Scratch (__device__ globals)
__device__ float g_r[N];
__device__ float g_zpart[SPL_A][NZ];
__device__ float g_rn[N];

// Fast tanh: 1 - 2/(exp(2x)+1). MUFU.EX2 + MUFU.RCP path, no branches.
__inline__ __device__ float ftanh(float x) {
    float e = __expf(2.0f * x);
    return 1.0f - __fdividef(2.0f, e + 1.0f);
}

__inline__ __device__ float dot4(float4 a, float4 b) {
    return a.x * b.x + a.y * b.y + a.z * b.z + a.w * b.w;
}

// Block reduce, up to 16 warps. Valid in thread 0.
__inline__ __device__ float block_reduce_w(float v, int nwarps) {
    __shared__ float sm[16];
    const int lane = threadIdx.x & 31;
    const int wid  = threadIdx.x >> 5;
    #pragma unroll
    for (int o = 16; o; o >>= 1) v += __shfl_down_sync(0xffffffffu, v, o);
    if (lane == 0) sm[wid] = v;
    __syncthreads();
    if (wid == 0) {
        v = (lane < nwarps) ? sm[lane] : 0.f;
        #pragma unroll
        for (int o = 8; o; o >>= 1) v += __shfl_down_sync(0xffffffffu, v, o);
    }
    return v;
}

// 4-wide block reduce, 8 warps (256 threads). Valid in thread 0.
__inline__ __device__ float4 block_reduce4(float4 v) {
    __shared__ float4 sm4[8];
    const int lane = threadIdx.x & 31;
    const int wid  = threadIdx.x >> 5;
    #pragma unroll
    for (int o = 16; o; o >>= 1) {
        v.x += __shfl_down_sync(0xffffffffu, v.x, o);
        v.y += __shfl_down_sync(0xffffffffu, v.y, o);
        v.z += __shfl_down_sync(0xffffffffu, v.z, o);
        v.w += __shfl_down_sync(0xffffffffu, v.w, o);
    }
    if (lane == 0) sm4[wid] = v;
    __syncthreads();
    if (wid == 0) {
        v = (lane < 8) ? sm4[lane] : make_float4(0.f, 0.f, 0.f, 0.f);
        #pragma unroll
        for (int o = 4; o; o >>= 1) {
            v.x += __shfl_down_sync(0xffffffffu, v.x, o);
            v.y += __shfl_down_sync(0xffffffffu, v.y, o);
            v.z += __shfl_down_sync(0xffffffffu, v.z, o);
            v.w += __shfl_down_sync(0xffffffffu, v.w, o);
        }
    }
    return v;
}

// ---------------------------------------------------------------------------
// Kernel 1: r = tanh(x+b) for split-owned chunks (row-group 0 persists g_r)
// + split-K partials of z = W_rz @ r for 4 rows/block.
// EARLY PDL trigger: dependents (k_big) may begin launching + prefetching
// W_rr while we compute.
// ---------------------------------------------------------------------------
__global__ void __launch_bounds__(256) k_rz(
    const float* __restrict__ x, const float* __restrict__ b,
    const float* __restrict__ W_rz)
{
    const int s    = blockIdx.x & (SPL_A - 1);
    const int rg   = blockIdx.x >> 3;
    const int row0 = rg * 4;
    const int c4   = s * CHA4 + threadIdx.x;

    float4 xv = ((const float4*)x)[c4];
    float4 bv = ((const float4*)b)[c4];

    const float4* w0 = (const float4*)(W_rz + (size_t)(row0 + 0) * N);
    const float4* w1 = (const float4*)(W_rz + (size_t)(row0 + 1) * N);
    const float4* w2 = (const float4*)(W_rz + (size_t)(row0 + 2) * N);
    const float4* w3 = (const float4*)(W_rz + (size_t)(row0 + 3) * N);
    float4 a0 = __ldcs(&w0[c4]);
    float4 a1 = __ldcs(&w1[c4]);
    float4 a2 = __ldcs(&w2[c4]);
    float4 a3 = __ldcs(&w3[c4]);

    // All loads issued — let k_big start launching/prefetching now.
    cudaTriggerProgrammaticLaunchCompletion();

    float4 r0;
    r0.x = ftanh(xv.x + bv.x); r0.y = ftanh(xv.y + bv.y);
    r0.z = ftanh(xv.z + bv.z); r0.w = ftanh(xv.w + bv.w);
    if (rg == 0) ((float4*)g_r)[c4] = r0;

    float4 acc = make_float4(dot4(a0, r0), dot4(a1, r0),
                             dot4(a2, r0), dot4(a3, r0));
    acc = block_reduce4(acc);
    if (threadIdx.x == 0) {
        g_zpart[s][row0 + 0] = acc.x;
        g_zpart[s][row0 + 1] = acc.y;
        g_zpart[s][row0 + 2] = acc.z;
        g_zpart[s][row0 + 3] = acc.w;
    }
}

// ---------------------------------------------------------------------------
// Kernel 2: fused row update (R9 structure, 8x LDG.128 front-batched).
// PDL: prefetch all k_rz-independent data before grid-sync; early trigger so
// k_tail can launch + prefetch during our drain.
// ---------------------------------------------------------------------------
__global__ void __launch_bounds__(256) k_big(
    const float* __restrict__ W_rr, const float* __restrict__ W_zr,
    const float* __restrict__ W_cr, const float* __restrict__ W_epsr,
    const float* __restrict__ x,    const float* __restrict__ eps,
    const float* __restrict__ c,    const float* __restrict__ b,
    float* __restrict__ out)
{
    const int row = blockIdx.x;
    const int t   = threadIdx.x;

    const float4* __restrict__ w = (const float4*)(W_rr + (size_t)row * N);
    const float4* __restrict__ v = (const float4*)g_r;

    // ---- independent prefetch (overlaps k_rz under PDL) ----
    float4 wv[8];
    #pragma unroll
    for (int i = 0; i < 8; i++) wv[i] = __ldcs(&w[t + i * 256]);

    float4 sidew = make_float4(0.f, 0.f, 0.f, 0.f);
    float4 sidev = make_float4(0.f, 0.f, 0.f, 0.f);
    if (t < 64) {
        sidew = __ldcs(((const float4*)(W_epsr + (size_t)row * NZ)) + t);
        sidev = ((const float4*)eps)[t];
    } else if (t < 128) {
        sidew = __ldcs(((const float4*)(W_zr + (size_t)row * NZ)) + (t - 64));
    } else if (t < 160) {
        sidew = __ldcs(((const float4*)(W_cr + (size_t)row * NC)) + (t - 128));
        sidev = ((const float4*)c)[t - 128];
    }

    // Loads issued — let k_tail start launching/prefetching.
    cudaTriggerProgrammaticLaunchCompletion();

    // ---- wait for k_rz's g_r / g_zpart ----
    cudaGridDependencySynchronize();

    float a0 = 0.f, a1 = 0.f, a2 = 0.f, a3 = 0.f;
    #pragma unroll
    for (int i = 0; i < 8; i++) {
        float d = dot4(wv[i], v[t + i * 256]);   // g_r: L1-hit after first block
        if ((i & 3) == 0) a0 += d;
        else if ((i & 3) == 1) a1 += d;
        else if ((i & 3) == 2) a2 += d;
        else a3 += d;
    }
    float acc = (a0 + a1) + (a2 + a3);

    if (t < 64) {                               // W_epsr row · eps
        acc += dot4(sidew, sidev);
    } else if (t < 128) {                       // W_zr row · z (fixed split order)
        const int k = t - 64;
        float4 q = ((const float4*)g_zpart[0])[k];
        #pragma unroll
        for (int s = 1; s < SPL_A; s++) {
            float4 p = ((const float4*)g_zpart[s])[k];
            q.x += p.x; q.y += p.y; q.z += p.z; q.w += p.w;
        }
        acc += dot4(sidew, q);
    } else if (t < 160) {                       // W_cr row · c
        acc += dot4(sidew, sidev);
    }

    acc = block_reduce_w(acc, 8);
    if (t == 0) {
        float xv = x[row];
        float xn = xv + DT_ * (acc - xv);
        out[row] = xn;
        float rn = ftanh(xn + b[row]);
        out[N + row] = rn;
        g_rn[row] = rn;
    }
}

// ---------------------------------------------------------------------------
// Kernel 3: z_new / c_new / eps_new. One block per output row, 512 threads.
// PDL: prefetch W row before grid-sync; read g_rn after.
// ---------------------------------------------------------------------------
__global__ void __launch_bounds__(512) k_tail(
    const float* __restrict__ W_rz, const float* __restrict__ W_rc,
    const float* __restrict__ z_tilde, float* __restrict__ out)
{
    const int idx = blockIdx.x;     // 0..383
    const float* __restrict__ Wrow = (idx < NZ)
        ? (W_rz + (size_t)idx * N)
        : (W_rc + (size_t)(idx - NZ) * N);
    const float4* __restrict__ w = (const float4*)Wrow;
    const float4* __restrict__ v = (const float4*)g_rn;
    const int base = threadIdx.x * 4;

    // ---- independent prefetch (overlaps k_big's drain under PDL) ----
    float4 w0 = __ldcs(&w[base + 0]), w1 = __ldcs(&w[base + 1]);
    float4 w2 = __ldcs(&w[base + 2]), w3 = __ldcs(&w[base + 3]);

    // ---- wait for k_big's g_rn ----
    cudaGridDependencySynchronize();

    float4 v0 = v[base + 0], v1 = v[base + 1];
    float4 v2 = v[base + 2], v3 = v[base + 3];

    float acc = (dot4(w0, v0) + dot4(w1, v1)) + (dot4(w2, v2) + dot4(w3, v3));
    acc = block_reduce_w(acc, 16);
    if (threadIdx.x == 0) {
        if (idx < NZ) {
            out[2 * N + idx] = acc;                          // z_new
            out[2 * N + NZ + NC + idx] = acc - z_tilde[idx]; // eps_new
        } else {
            out[2 * N + NZ + (idx - NZ)] = acc;              // c_new
        }
    }
}

extern "C" void kernel_launch(void* const* d_in, const int* in_sizes, int n_in,
                              void* d_out, int out_size) {
    // metadata order: x, eps, c, z_tilde, W_rr, W_zr, W_cr, W_epsr, W_rz, W_rc, b
    const float* x       = (const float*)d_in[0];
    const float* eps     = (const float*)d_in[1];
    const float* c       = (const float*)d_in[2];
    const float* z_tilde = (const float*)d_in[3];
    const float* W_rr    = (const float*)d_in[4];
    const float* W_zr    = (const float*)d_in[5];
    const float* W_cr    = (const float*)d_in[6];
    const float* W_epsr  = (const float*)d_in[7];
    const float* W_rz    = (const float*)d_in[8];
    const float* W_rc    = (const float*)d_in[9];
    const float* b       = (const float*)d_in[10];
    float* out = (float*)d_out;

    k_rz<<<(NZ / 4) * SPL_A, 256>>>(x, b, W_rz);

    // k_big with PDL (fallback to plain launch if unsupported)
    {
        cudaLaunchConfig_t cfg = {};
        cfg.gridDim  = dim3(N);
        cfg.blockDim = dim3(256);
        cfg.dynamicSmemBytes = 0;
        cfg.stream = 0;
        cudaLaunchAttribute at[1];
        at[0].id = cudaLaunchAttributeProgrammaticStreamSerialization;
        at[0].val.programmaticStreamSerializationAllowed = 1;
        cfg.attrs = at; cfg.numAttrs = 1;
        cudaError_t e = cudaLaunchKernelEx(&cfg, k_big, W_rr, W_zr, W_cr,
                                           W_epsr, x, eps, c, b, out);
        if (e != cudaSuccess) {
            (void)cudaGetLastError();
            k_big<<<N, 256>>>(W_rr, W_zr, W_cr, W_epsr, x, eps, c, b, out);
        }
    }

    // k_tail with PDL (same fallback)
    {
        cudaLaunchConfig_t cfg = {};
        cfg.gridDim  = dim3(NZ + NC);
        cfg.blockDim = dim3(512);
        cfg.dynamicSmemBytes = 0;
        cfg.stream = 0;
        cudaLaunchAttribute at[1];
        at[0].id = cudaLaunchAttributeProgrammaticStreamSerialization;
        at[0].val.programmaticStreamSerializationAllowed = 1;
        cfg.attrs = at; cfg.numAttrs = 1;
        cudaError_t e = cudaLaunchKernelEx(&cfg, k_tail, W_rz, W_rc, z_tilde, out);
        if (e != cudaSuccess) {
            (void)cudaGetLastError();
            k_tail<<<NZ + NC, 512>>>(W_rz, W_rc, z_tilde, out);
        }
    }
}